// round 8
// baseline (speedup 1.0000x reference)
#include <cuda_runtime.h>
#include <math.h>

#define Nn   6000
#define Ee   192000
#define CINc 32
#define CHID 64
#define Kk   125          // 5^3 kernel weights
// S = 8 corners per edge

// ---------------- device scratch (no allocation allowed) ----------------
__device__ float g_Tx[(size_t)Nn * Kk * CINc];   // 24M floats, pre-scaled by 1/deg
__device__ float g_Th[(size_t)Nn * Kk * CHID];   // 48M floats, pre-scaled by 1/deg
__device__ int   g_deg[Nn];
__device__ int   g_fill[Nn];
__device__ int   g_rowstart[Nn + 1];
__device__ int   g_csr[Ee];
__device__ int   g_bidx[Ee * 8];
__device__ float g_bval[Ee * 8];
__device__ float g_XR[Nn * CHID];
__device__ float g_XZ[Nn * CHID];
__device__ float g_XN[Nn * CHID];
__device__ float g_HR[Nn * CHID];
__device__ float g_HZ[Nn * CHID];

// ---------------- f32x2 packed math helpers ----------------
__device__ __forceinline__ unsigned long long ffma2(unsigned long long a,
                                                    unsigned long long b,
                                                    unsigned long long c) {
    unsigned long long d;
    asm("fma.rn.f32x2 %0, %1, %2, %3;" : "=l"(d) : "l"(a), "l"(b), "l"(c));
    return d;
}
__device__ __forceinline__ unsigned long long packdup(float f) {
    unsigned long long r;
    asm("mov.b64 %0, {%1, %1};" : "=l"(r) : "f"(f));
    return r;
}
__device__ __forceinline__ void unpack2(unsigned long long v, float& lo, float& hi) {
    asm("mov.b64 {%0, %1}, %2;" : "=f"(lo), "=f"(hi) : "l"(v));
}

// ---------------- kernel 0: zero per-call counters ----------------
__global__ void k_zero() {
    int i = blockIdx.x * blockDim.x + threadIdx.x;
    if (i < Nn) { g_deg[i] = 0; g_fill[i] = 0; }
}

// ---------------- kernel 1: per-edge basis/index + degree histogram ----------------
__global__ void k_edge(const float* __restrict__ attr, const int* __restrict__ ei) {
    int e = blockIdx.x * blockDim.x + threadIdx.x;
    if (e >= Ee) return;
    float fr[3]; int i0[3];
#pragma unroll
    for (int d = 0; d < 3; d++) {
        float u = attr[e * 3 + d] * 4.0f;          // (KS-1) intervals
        int i = (int)floorf(u);
        i = i < 0 ? 0 : (i > 3 ? 3 : i);           // clip to [0, KS-2]
        fr[d] = u - (float)i;
        i0[d] = i;
    }
#pragma unroll
    for (int s = 0; s < 8; s++) {
        int b0 = s & 1, b1 = (s >> 1) & 1, b2 = (s >> 2) & 1;
        // strides = KS**[2,1,0] applied to dims [0,1,2]
        int idx = (i0[0] + b0) * 25 + (i0[1] + b1) * 5 + (i0[2] + b2);
        float w = (b0 ? fr[0] : 1.0f - fr[0]) *
                  (b1 ? fr[1] : 1.0f - fr[1]) *
                  (b2 ? fr[2] : 1.0f - fr[2]);
        g_bidx[e * 8 + s] = idx;
        g_bval[e * 8 + s] = w;
    }
    atomicAdd(&g_deg[ei[Ee + e]], 1);              // dst = row 1
}

// ---------------- kernel 2: exclusive scan of degrees (single block) ----------------
__global__ void k_scan() {
    __shared__ int sh[1024];
    int tid = threadIdx.x;
    const int CH = 6;                               // 1024*6 >= 6000
    int base = tid * CH;
    int local[CH];
    int sum = 0;
#pragma unroll
    for (int q = 0; q < CH; q++) {
        int i = base + q;
        int v = (i < Nn) ? g_deg[i] : 0;
        local[q] = sum;
        sum += v;
    }
    sh[tid] = sum;
    __syncthreads();
    for (int off = 1; off < 1024; off <<= 1) {
        int v = 0;
        if (tid >= off) v = sh[tid - off];
        __syncthreads();
        sh[tid] += v;
        __syncthreads();
    }
    int excl = (tid > 0) ? sh[tid - 1] : 0;
#pragma unroll
    for (int q = 0; q < CH; q++) {
        int i = base + q;
        if (i < Nn) g_rowstart[i] = excl + local[q];
    }
    if (tid == 1023) g_rowstart[Nn] = sh[1023];
}

// ---------------- kernel 3: CSR fill ----------------
__global__ void k_fill(const int* __restrict__ ei) {
    int e = blockIdx.x * blockDim.x + threadIdx.x;
    if (e >= Ee) return;
    int dst = ei[Ee + e];
    int p = atomicAdd(&g_fill[dst], 1);
    g_csr[g_rowstart[dst] + p] = e;
}

// ---------------- kernel 4: per-node scatter into T (no atomics), pre-scaled by 1/deg ----------------
__global__ __launch_bounds__(96) void k_scatter(const float* __restrict__ x,
                                                const float* __restrict__ hidden,
                                                const int* __restrict__ ei) {
    __shared__ float Tsh[Kk * 96];                  // 48000 bytes
    int n = blockIdx.x;
    int c = threadIdx.x;                            // channel lane: 0..31 -> x, 32..95 -> hidden
#pragma unroll 5
    for (int k = 0; k < Kk; k++) Tsh[k * 96 + c] = 0.0f;
    int rs = g_rowstart[n], re = g_rowstart[n + 1];
    float inv = 1.0f / (float)max(re - rs, 1);
    __syncthreads();

    for (int j = rs; j < re; j++) {
        int e   = __ldg(&g_csr[j]);
        int src = __ldg(&ei[e]);                    // src = row 0
        float xv = (c < CINc) ? __ldg(&x[src * CINc + c])
                              : __ldg(&hidden[src * CHID + (c - CINc)]);
        const int4*   bip = (const int4*)(g_bidx + e * 8);
        const float4* bvp = (const float4*)(g_bval + e * 8);
        int4   ia = __ldg(bip),     ib = __ldg(bip + 1);
        float4 va = __ldg(bvp),     vb = __ldg(bvp + 1);
        // 8 corner indices within an edge are distinct; each thread owns column c
        Tsh[ia.x * 96 + c] += va.x * xv;
        Tsh[ia.y * 96 + c] += va.y * xv;
        Tsh[ia.z * 96 + c] += va.z * xv;
        Tsh[ia.w * 96 + c] += va.w * xv;
        Tsh[ib.x * 96 + c] += vb.x * xv;
        Tsh[ib.y * 96 + c] += vb.y * xv;
        Tsh[ib.z * 96 + c] += vb.z * xv;
        Tsh[ib.w * 96 + c] += vb.w * xv;
    }
    __syncthreads();

    if (c < CINc) {
        float* o = g_Tx + (size_t)n * (Kk * CINc) + c;
#pragma unroll 5
        for (int k = 0; k < Kk; k++) o[k * CINc] = Tsh[k * 96 + c] * inv;
    } else {
        float* o = g_Th + (size_t)n * (Kk * CHID) + (c - CINc);
#pragma unroll 5
        for (int k = 0; k < Kk; k++) o[k * CHID] = Tsh[k * 96 + c] * inv;
    }
}

// ---------------- kernel 5: GEMM  C[M,64] = [T/deg | X2] @ [W ; root] + bias ----------------
// BM=64, BN=64, BK=16, 64 threads, 8x8 thread tile, f32x2 row-pair accumulators.
// grid.y selects one of the 5 convs (hn-conv is dead in the reference).
__global__ __launch_bounds__(64) void k_gemm(
    const float* __restrict__ x, const float* __restrict__ hidden,
    const float* __restrict__ Wxr, const float* __restrict__ Rxr, const float* __restrict__ Bxr,
    const float* __restrict__ Wxz, const float* __restrict__ Rxz, const float* __restrict__ Bxz,
    const float* __restrict__ Wxn, const float* __restrict__ Rxn, const float* __restrict__ Bxn,
    const float* __restrict__ Whr, const float* __restrict__ Rhr, const float* __restrict__ Bhr,
    const float* __restrict__ Whz, const float* __restrict__ Rhz, const float* __restrict__ Bhz)
{
    const float *A, *X2, *W, *R, *B;
    float* O;
    int Kd, C2;
    switch (blockIdx.y) {
        case 0:  A = g_Tx; X2 = x;      W = Wxr; R = Rxr; B = Bxr; O = g_XR; Kd = Kk * CINc; C2 = CINc; break;
        case 1:  A = g_Tx; X2 = x;      W = Wxz; R = Rxz; B = Bxz; O = g_XZ; Kd = Kk * CINc; C2 = CINc; break;
        case 2:  A = g_Tx; X2 = x;      W = Wxn; R = Rxn; B = Bxn; O = g_XN; Kd = Kk * CINc; C2 = CINc; break;
        case 3:  A = g_Th; X2 = hidden; W = Whr; R = Rhr; B = Bhr; O = g_HR; Kd = Kk * CHID; C2 = CHID; break;
        default: A = g_Th; X2 = hidden; W = Whz; R = Rhz; B = Bhz; O = g_HZ; Kd = Kk * CHID; C2 = CHID; break;
    }
    __shared__ float As[16][64];
    __shared__ float Bs[16][64];
    int t = threadIdx.x, tx = t & 7, ty = t >> 3;
    int row0 = blockIdx.x * 64;
    int m = row0 + t;
    int kbrow = t >> 2, c0 = (t & 3) * 16;

    unsigned long long acc[4][8];
#pragma unroll
    for (int i = 0; i < 4; i++)
#pragma unroll
        for (int j = 0; j < 8; j++) acc[i][j] = 0ull;

    int ntile = (Kd + C2) >> 4;                     // 252 (x) or 504 (h), no tile straddles Kd
    float4 av[4], bv[4];

    auto loadT = [&](int kt) {
        int k0 = kt * 16;
        if (m < Nn) {
            const float* ap = (k0 < Kd) ? (A + (size_t)m * Kd + k0)
                                        : (X2 + (size_t)m * C2 + (k0 - Kd));
#pragma unroll
            for (int q = 0; q < 4; q++) av[q] = __ldg((const float4*)ap + q);
        } else {
            float4 z = make_float4(0.f, 0.f, 0.f, 0.f);
            av[0] = z; av[1] = z; av[2] = z; av[3] = z;
        }
        int kk = k0 + kbrow;
        const float* bp = (kk < Kd) ? (W + (size_t)kk * 64 + c0)
                                    : (R + (size_t)(kk - Kd) * 64 + c0);
#pragma unroll
        for (int q = 0; q < 4; q++) bv[q] = __ldg((const float4*)bp + q);
    };
    auto storeT = [&]() {
#pragma unroll
        for (int q = 0; q < 4; q++) {
            As[4 * q + 0][t] = av[q].x;
            As[4 * q + 1][t] = av[q].y;
            As[4 * q + 2][t] = av[q].z;
            As[4 * q + 3][t] = av[q].w;
        }
#pragma unroll
        for (int q = 0; q < 4; q++) *(float4*)&Bs[kbrow][c0 + 4 * q] = bv[q];
    };

    loadT(0);
    storeT();
    __syncthreads();
    for (int kt = 0; kt < ntile; kt++) {
        bool more = (kt + 1 < ntile);
        if (more) loadT(kt + 1);                    // LDG latency overlapped with compute
#pragma unroll
        for (int k = 0; k < 16; k++) {
            unsigned long long a2[4];
#pragma unroll
            for (int rp = 0; rp < 4; rp++)
                a2[rp] = *(const unsigned long long*)&As[k][ty * 8 + 2 * rp];
            float4 bA = *(const float4*)&Bs[k][tx * 8];
            float4 bB = *(const float4*)&Bs[k][tx * 8 + 4];
            unsigned long long bb[8];
            bb[0] = packdup(bA.x); bb[1] = packdup(bA.y);
            bb[2] = packdup(bA.z); bb[3] = packdup(bA.w);
            bb[4] = packdup(bB.x); bb[5] = packdup(bB.y);
            bb[6] = packdup(bB.z); bb[7] = packdup(bB.w);
#pragma unroll
            for (int rp = 0; rp < 4; rp++)
#pragma unroll
                for (int j = 0; j < 8; j++)
                    acc[rp][j] = ffma2(a2[rp], bb[j], acc[rp][j]);
        }
        __syncthreads();
        if (more) { storeT(); __syncthreads(); }
    }

    // epilogue: add bias, write two rows per row-pair
    float bias8[8];
#pragma unroll
    for (int j = 0; j < 8; j++) bias8[j] = __ldg(&B[tx * 8 + j]);
#pragma unroll
    for (int rp = 0; rp < 4; rp++) {
        float r0[8], r1[8];
#pragma unroll
        for (int j = 0; j < 8; j++) {
            float lo, hi;
            unpack2(acc[rp][j], lo, hi);
            r0[j] = lo + bias8[j];
            r1[j] = hi + bias8[j];
        }
        int m0 = row0 + ty * 8 + 2 * rp;
        if (m0 < Nn) {
            float4* op = (float4*)(O + (size_t)m0 * 64 + tx * 8);
            op[0] = make_float4(r0[0], r0[1], r0[2], r0[3]);
            op[1] = make_float4(r0[4], r0[5], r0[6], r0[7]);
        }
        if (m0 + 1 < Nn) {
            float4* op = (float4*)(O + (size_t)(m0 + 1) * 64 + tx * 8);
            op[0] = make_float4(r1[0], r1[1], r1[2], r1[3]);
            op[1] = make_float4(r1[4], r1[5], r1[6], r1[7]);
        }
    }
}

// ---------------- kernel 6: GRU gate fusion ----------------
__global__ void k_gates(const float* __restrict__ hidden, float* __restrict__ out) {
    int i = blockIdx.x * blockDim.x + threadIdx.x;
    if (i >= Nn * CHID) return;
    float xr = g_XR[i], hr = g_HR[i];
    float xz = g_XZ[i], hz = g_HZ[i];
    float xn = g_XN[i], h = hidden[i];
    float r = 1.0f / (1.0f + expf(-(xr + hr)));
    float z = 1.0f / (1.0f + expf(-(xz + hz)));
    float n = tanhf(xn + r * hr);                   // faithful to the reference's hr reuse
    out[i] = (1.0f - z) * n + z * h;
}

// ---------------- launch ----------------
extern "C" void kernel_launch(void* const* d_in, const int* in_sizes, int n_in,
                              void* d_out, int out_size) {
    const float* x      = (const float*)d_in[0];
    const float* hidden = (const float*)d_in[1];
    const int*   ei     = (const int*)d_in[2];
    const float* attr   = (const float*)d_in[3];
    const float* Wxr = (const float*)d_in[4];
    const float* Rxr = (const float*)d_in[5];
    const float* Bxr = (const float*)d_in[6];
    const float* Whr = (const float*)d_in[7];
    const float* Rhr = (const float*)d_in[8];
    const float* Bhr = (const float*)d_in[9];
    const float* Wxz = (const float*)d_in[10];
    const float* Rxz = (const float*)d_in[11];
    const float* Bxz = (const float*)d_in[12];
    const float* Whz = (const float*)d_in[13];
    const float* Rhz = (const float*)d_in[14];
    const float* Bhz = (const float*)d_in[15];
    const float* Wxn = (const float*)d_in[16];
    const float* Rxn = (const float*)d_in[17];
    const float* Bxn = (const float*)d_in[18];
    // d_in[19..21] = W_hn/root_hn/b_hn: dead in the reference (hr reuse bug), unused.
    float* out = (float*)d_out;
    (void)in_sizes; (void)n_in; (void)out_size;

    k_zero<<<(Nn + 255) / 256, 256>>>();
    k_edge<<<(Ee + 255) / 256, 256>>>(attr, ei);
    k_scan<<<1, 1024>>>();
    k_fill<<<(Ee + 255) / 256, 256>>>(ei);
    k_scatter<<<Nn, 96>>>(x, hidden, ei);
    dim3 gg((Nn + 63) / 64, 5);
    k_gemm<<<gg, 64>>>(x, hidden,
                       Wxr, Rxr, Bxr,
                       Wxz, Rxz, Bxz,
                       Wxn, Rxn, Bxn,
                       Whr, Rhr, Bhr,
                       Whz, Rhz, Bhz);
    k_gates<<<(Nn * CHID + 255) / 256, 256>>>(hidden, out);
}

// round 10
// speedup vs baseline: 2.5302x; 2.5302x over previous
#include <cuda_runtime.h>
#include <math.h>
#include <stdint.h>

#define Nn   6000
#define Ee   192000
#define CINc 32
#define CHID 64
#define Kk   125
#define KX   4000        // Kk*CINc
#define KH   8000        // Kk*CHID

// ---------------- device scratch ----------------
__device__ float g_Tx[(size_t)Nn * KX];     // tf32-rounded, pre-scaled by 1/deg
__device__ float g_Th[(size_t)Nn * KH];
__device__ float g_Btx[192 * KX];           // [co,k]: {Wxr,Wxz,Wxn} transposed, tf32-rounded
__device__ float g_Bth[128 * KH];           // [co,k]: {Whr,Whz} transposed
__device__ float g_part[7][Nn * CHID];      // 0=XR 1=XZ 2=XN 3,4=HR halves 5,6=HZ halves
__device__ int   g_deg[Nn];
__device__ int   g_fill[Nn];
__device__ int   g_rowstart[Nn + 1];
__device__ int   g_csr[Ee];
__device__ int   g_bidx[Ee * 8];
__device__ float g_bval[Ee * 8];

// ---------------- PTX helpers (compute_103-safe: sm_80+ features only) ----------------
__device__ __forceinline__ uint32_t smem_u32(const void* p) {
    uint32_t a;
    asm("{ .reg .u64 t; cvta.to.shared.u64 t, %1; cvt.u32.u64 %0, t; }" : "=r"(a) : "l"(p));
    return a;
}
__device__ __forceinline__ float to_tf32(float f) {
    asm("cvt.rna.tf32.f32 %0, %0;" : "+f"(f));
    return f;
}
__device__ __forceinline__ void cpasync16(uint32_t dst, const void* src, int src_bytes) {
    asm volatile("cp.async.cg.shared.global [%0], [%1], 16, %2;"
                 :: "r"(dst), "l"(src), "r"(src_bytes) : "memory");
}
#define CP_COMMIT() asm volatile("cp.async.commit_group;" ::: "memory")
#define WAITG(n)    asm volatile("cp.async.wait_group " #n ";" ::: "memory")

__device__ __forceinline__ uint32_t lds32(uint32_t a) {
    uint32_t v;
    asm volatile("ld.shared.b32 %0, [%1];" : "=r"(v) : "r"(a));
    return v;
}
__device__ __forceinline__ void mma8(float* d, const uint32_t* a, uint32_t b0, uint32_t b1) {
    asm volatile(
        "mma.sync.aligned.m16n8k8.row.col.f32.tf32.tf32.f32 "
        "{%0,%1,%2,%3}, {%4,%5,%6,%7}, {%8,%9}, {%0,%1,%2,%3};"
        : "+f"(d[0]), "+f"(d[1]), "+f"(d[2]), "+f"(d[3])
        : "r"(a[0]), "r"(a[1]), "r"(a[2]), "r"(a[3]), "r"(b0), "r"(b1));
}

// ---------------- kernel 0: zero per-call counters ----------------
__global__ void k_zero() {
    int i = blockIdx.x * blockDim.x + threadIdx.x;
    if (i < Nn) { g_deg[i] = 0; g_fill[i] = 0; }
}

// ---------------- kernel 1: per-edge basis/index + degree histogram ----------------
__global__ void k_edge(const float* __restrict__ attr, const int* __restrict__ ei) {
    int e = blockIdx.x * blockDim.x + threadIdx.x;
    if (e >= Ee) return;
    float fr[3]; int i0[3];
#pragma unroll
    for (int d = 0; d < 3; d++) {
        float u = attr[e * 3 + d] * 4.0f;
        int i = (int)floorf(u);
        i = i < 0 ? 0 : (i > 3 ? 3 : i);
        fr[d] = u - (float)i;
        i0[d] = i;
    }
#pragma unroll
    for (int s = 0; s < 8; s++) {
        int b0 = s & 1, b1 = (s >> 1) & 1, b2 = (s >> 2) & 1;
        int idx = (i0[0] + b0) * 25 + (i0[1] + b1) * 5 + (i0[2] + b2);
        float w = (b0 ? fr[0] : 1.0f - fr[0]) *
                  (b1 ? fr[1] : 1.0f - fr[1]) *
                  (b2 ? fr[2] : 1.0f - fr[2]);
        g_bidx[e * 8 + s] = idx;
        g_bval[e * 8 + s] = w;
    }
    atomicAdd(&g_deg[ei[Ee + e]], 1);
}

// ---------------- kernel 2: exclusive scan (single block) ----------------
__global__ void k_scan() {
    __shared__ int sh[1024];
    int tid = threadIdx.x;
    const int CH = 6;
    int base = tid * CH;
    int local[CH];
    int sum = 0;
#pragma unroll
    for (int q = 0; q < CH; q++) {
        int i = base + q;
        int v = (i < Nn) ? g_deg[i] : 0;
        local[q] = sum;
        sum += v;
    }
    sh[tid] = sum;
    __syncthreads();
    for (int off = 1; off < 1024; off <<= 1) {
        int v = 0;
        if (tid >= off) v = sh[tid - off];
        __syncthreads();
        sh[tid] += v;
        __syncthreads();
    }
    int excl = (tid > 0) ? sh[tid - 1] : 0;
#pragma unroll
    for (int q = 0; q < CH; q++) {
        int i = base + q;
        if (i < Nn) g_rowstart[i] = excl + local[q];
    }
    if (tid == 1023) g_rowstart[Nn] = sh[1023];
}

// ---------------- kernel 3: CSR fill ----------------
__global__ void k_fill(const int* __restrict__ ei) {
    int e = blockIdx.x * blockDim.x + threadIdx.x;
    if (e >= Ee) return;
    int dst = ei[Ee + e];
    int p = atomicAdd(&g_fill[dst], 1);
    g_csr[g_rowstart[dst] + p] = e;
}

// ---------------- kernel 4: per-node scatter into T (no atomics), scaled + tf32-rounded ----------------
__global__ __launch_bounds__(96) void k_scatter(const float* __restrict__ x,
                                                const float* __restrict__ hidden,
                                                const int* __restrict__ ei) {
    __shared__ float Tsh[Kk * 96];
    int n = blockIdx.x;
    int c = threadIdx.x;
#pragma unroll 5
    for (int k = 0; k < Kk; k++) Tsh[k * 96 + c] = 0.0f;
    int rs = g_rowstart[n], re = g_rowstart[n + 1];
    float inv = 1.0f / (float)max(re - rs, 1);
    __syncthreads();

    for (int j = rs; j < re; j++) {
        int e   = __ldg(&g_csr[j]);
        int src = __ldg(&ei[e]);
        float xv = (c < CINc) ? __ldg(&x[src * CINc + c])
                              : __ldg(&hidden[src * CHID + (c - CINc)]);
        const int4*   bip = (const int4*)(g_bidx + e * 8);
        const float4* bvp = (const float4*)(g_bval + e * 8);
        int4   ia = __ldg(bip),     ib = __ldg(bip + 1);
        float4 va = __ldg(bvp),     vb = __ldg(bvp + 1);
        Tsh[ia.x * 96 + c] += va.x * xv;
        Tsh[ia.y * 96 + c] += va.y * xv;
        Tsh[ia.z * 96 + c] += va.z * xv;
        Tsh[ia.w * 96 + c] += va.w * xv;
        Tsh[ib.x * 96 + c] += vb.x * xv;
        Tsh[ib.y * 96 + c] += vb.y * xv;
        Tsh[ib.z * 96 + c] += vb.z * xv;
        Tsh[ib.w * 96 + c] += vb.w * xv;
    }
    __syncthreads();

    if (c < CINc) {
        float* o = g_Tx + (size_t)n * KX + c;
#pragma unroll 5
        for (int k = 0; k < Kk; k++) o[k * CINc] = to_tf32(Tsh[k * 96 + c] * inv);
    } else {
        float* o = g_Th + (size_t)n * KH + (c - CINc);
#pragma unroll 5
        for (int k = 0; k < Kk; k++) o[k * CHID] = to_tf32(Tsh[k * 96 + c] * inv);
    }
}

// ---------------- kernel 5: transpose W -> Bt [N,K] K-major, tf32-rounded ----------------
__global__ void k_transpose(const float* __restrict__ Wxr, const float* __restrict__ Wxz,
                            const float* __restrict__ Wxn, const float* __restrict__ Whr,
                            const float* __restrict__ Whz) {
    __shared__ float sh[32][65];
    int conv = blockIdx.y;
    const float* W; float* dst; int Kd;
    switch (conv) {
        case 0:  W = Wxr; dst = g_Btx;                     Kd = KX; break;
        case 1:  W = Wxz; dst = g_Btx + (size_t)64 * KX;   Kd = KX; break;
        case 2:  W = Wxn; dst = g_Btx + (size_t)128 * KX;  Kd = KX; break;
        case 3:  W = Whr; dst = g_Bth;                     Kd = KH; break;
        default: W = Whz; dst = g_Bth + (size_t)64 * KH;   Kd = KH; break;
    }
    int k0 = blockIdx.x * 32;
    if (k0 >= Kd) return;
    int tid = threadIdx.x;
#pragma unroll
    for (int w = 0; w < 8; w++) {
        int idx = w * 256 + tid, kk = idx >> 6, c = idx & 63;
        sh[kk][c] = W[(size_t)(k0 + kk) * 64 + c];
    }
    __syncthreads();
#pragma unroll
    for (int w = 0; w < 8; w++) {
        int idx = w * 256 + tid, c = idx >> 5, kk = idx & 31;
        dst[(size_t)c * Kd + k0 + kk] = to_tf32(sh[kk][c]);
    }
}

// ---------------- kernel 6: tf32 mma.sync GEMM ----------------
// BM=64, BK=32, 256 threads = 8 warps (2M x 4N). Double-buffered cp.async.
// Smem rows padded to 36 words (144B): 16B-aligned for cp.async AND
// (4*gid + tig) % 32 covers all banks -> conflict-free fragment LDS.
// Stage: A[64][36] @0 (9216B), B[NG*64][36] @9216. STAGE=36864, x2 = 73728B.
#define STAGE 36864

template<int NG>
__device__ __forceinline__ void gemm_body(const float* __restrict__ A,
                                          const float* __restrict__ Bt,
                                          int Kd, int kc0, int row0,
                                          int pbase, int pstride, uint32_t sb) {
    const int NT = NG * 2;                       // 8-wide N subtiles per warp
    int t = threadIdx.x;
    int w = t >> 5, lane = t & 31;
    int wm = w & 1, wn = w >> 1;
    int gid = lane >> 2, tig = lane & 3;

    float acc[2][NT][4];
#pragma unroll
    for (int mt = 0; mt < 2; mt++)
#pragma unroll
        for (int nt = 0; nt < NT; nt++)
#pragma unroll
            for (int q = 0; q < 4; q++) acc[mt][nt][q] = 0.0f;

    auto ldchunk = [&](int kc, int s) {
        uint32_t Ab = sb + s * STAGE;
        uint32_t Bb = Ab + 9216;
        int kb = kc * 32;
#pragma unroll
        for (int q = 0; q < 2; q++) {
            int idx = q * 256 + t, row = idx >> 3, c4 = idx & 7;
            int m = row0 + row;
            int mc = m < Nn ? m : 0;
            cpasync16(Ab + (uint32_t)(row * 144 + c4 * 16),
                      A + (size_t)mc * Kd + kb + c4 * 4, m < Nn ? 16 : 0);
        }
#pragma unroll
        for (int q = 0; q < 2 * NG; q++) {
            int idx = q * 256 + t, row = idx >> 3, c4 = idx & 7;
            cpasync16(Bb + (uint32_t)(row * 144 + c4 * 16),
                      Bt + (size_t)row * Kd + kb + c4 * 4, 16);
        }
        CP_COMMIT();
    };

    auto compute = [&](int s) {
        uint32_t Ab = sb + s * STAGE;
        uint32_t Bb = Ab + 9216;
#pragma unroll
        for (int ks = 0; ks < 4; ks++) {
            uint32_t af[2][4];
#pragma unroll
            for (int mt = 0; mt < 2; mt++) {
                uint32_t base = Ab + (uint32_t)((wm * 32 + mt * 16 + gid) * 144 +
                                                (ks * 8 + tig) * 4);
                af[mt][0] = lds32(base);            // (g,     tig)
                af[mt][1] = lds32(base + 8 * 144);  // (g+8,   tig)
                af[mt][2] = lds32(base + 16);       // (g,     tig+4)
                af[mt][3] = lds32(base + 8 * 144 + 16);
            }
#pragma unroll
            for (int nt = 0; nt < NT; nt++) {
                uint32_t bb = Bb + (uint32_t)((wn * NT * 8 + nt * 8 + gid) * 144 +
                                              (ks * 8 + tig) * 4);
                uint32_t b0 = lds32(bb);            // B[k=tig,   n=gid]
                uint32_t b1 = lds32(bb + 16);       // B[k=tig+4, n=gid]
#pragma unroll
                for (int mt = 0; mt < 2; mt++)
                    mma8(acc[mt][nt], af[mt], b0, b1);
            }
        }
    };

    ldchunk(kc0, 0);
    ldchunk(kc0 + 1, 1);
#pragma unroll 1
    for (int i = 0; i < 125; i++) {
        if (i < 124) { WAITG(1); } else { WAITG(0); }
        __syncthreads();
        compute(i & 1);
        __syncthreads();
        if (i < 123) ldchunk(kc0 + i + 2, i & 1);
    }

    // epilogue: c0,c1 -> (row g, cols 2tig,2tig+1); c2,c3 -> row g+8
#pragma unroll
    for (int mt = 0; mt < 2; mt++)
#pragma unroll
        for (int nt = 0; nt < NT; nt++) {
            int gcol = wn * NT * 8 + nt * 8 + tig * 2;
            int g = gcol >> 6, cc = gcol & 63;
            float* O = g_part[pbase + g * pstride];
            int r = row0 + wm * 32 + mt * 16 + gid;
            if (r < Nn)
                *(float2*)&O[(size_t)r * 64 + cc] =
                    make_float2(acc[mt][nt][0], acc[mt][nt][1]);
            if (r + 8 < Nn)
                *(float2*)&O[(size_t)(r + 8) * 64 + cc] =
                    make_float2(acc[mt][nt][2], acc[mt][nt][3]);
        }
}

// grid = 282: blocks [0,188) h-pass (94 M-tiles x 2 K-halves), [188,282) x-pass.
__global__ void __launch_bounds__(256, 2) k_gemm_mma() {
    extern __shared__ char smem[];
    uint32_t sb = smem_u32(smem);
    int bx = blockIdx.x;
    if (bx < 188) {
        int mt = bx >> 1, half = bx & 1;
        gemm_body<2>(g_Th, g_Bth, KH, half * 125, mt * 64, 3 + half, 2, sb);
    } else {
        gemm_body<3>(g_Tx, g_Btx, KX, 0, (bx - 188) * 64, 0, 1, sb);
    }
}

// ---------------- kernel 7: root GEMVs (fp32) + bias + GRU gates ----------------
__global__ void k_gates(const float* __restrict__ x, const float* __restrict__ hidden,
                        const float* __restrict__ Rxr, const float* __restrict__ Bxr,
                        const float* __restrict__ Rxz, const float* __restrict__ Bxz,
                        const float* __restrict__ Rxn, const float* __restrict__ Bxn,
                        const float* __restrict__ Rhr, const float* __restrict__ Bhr,
                        const float* __restrict__ Rhz, const float* __restrict__ Bhz,
                        float* __restrict__ out) {
    __shared__ float xs[4][32];
    __shared__ float hs[4][64];
    int tid = threadIdx.x;
    int nb = blockIdx.x * 4;
    if (tid < 128) {
        int nl = tid >> 5, i = tid & 31, n = nb + nl;
        xs[nl][i] = (n < Nn) ? x[n * 32 + i] : 0.f;
    }
    {
        int nl = tid >> 6, c = tid & 63, n = nb + nl;
        hs[nl][c] = (n < Nn) ? hidden[n * 64 + c] : 0.f;
    }
    __syncthreads();
    int nl = tid >> 6, c = tid & 63, n = nb + nl;
    if (n >= Nn) return;
    size_t i = (size_t)n * 64 + c;
    float xr = g_part[0][i] + Bxr[c];
    float xz = g_part[1][i] + Bxz[c];
    float xn = g_part[2][i] + Bxn[c];
    float hr = g_part[3][i] + g_part[4][i] + Bhr[c];
    float hz = g_part[5][i] + g_part[6][i] + Bhz[c];
#pragma unroll 8
    for (int k = 0; k < 32; k++) {
        float xv = xs[nl][k];
        xr += xv * Rxr[k * 64 + c];
        xz += xv * Rxz[k * 64 + c];
        xn += xv * Rxn[k * 64 + c];
    }
#pragma unroll 8
    for (int k = 0; k < 64; k++) {
        float hv = hs[nl][k];
        hr += hv * Rhr[k * 64 + c];
        hz += hv * Rhz[k * 64 + c];
    }
    float r = 1.0f / (1.0f + expf(-(xr + hr)));
    float z = 1.0f / (1.0f + expf(-(xz + hz)));
    float nno = tanhf(xn + r * hr);                 // faithful hr reuse
    out[i] = (1.0f - z) * nno + z * hs[nl][c];
}

// ---------------- launch ----------------
extern "C" void kernel_launch(void* const* d_in, const int* in_sizes, int n_in,
                              void* d_out, int out_size) {
    const float* x      = (const float*)d_in[0];
    const float* hidden = (const float*)d_in[1];
    const int*   ei     = (const int*)d_in[2];
    const float* attr   = (const float*)d_in[3];
    const float* Wxr = (const float*)d_in[4];
    const float* Rxr = (const float*)d_in[5];
    const float* Bxr = (const float*)d_in[6];
    const float* Whr = (const float*)d_in[7];
    const float* Rhr = (const float*)d_in[8];
    const float* Bhr = (const float*)d_in[9];
    const float* Wxz = (const float*)d_in[10];
    const float* Rxz = (const float*)d_in[11];
    const float* Bxz = (const float*)d_in[12];
    const float* Whz = (const float*)d_in[13];
    const float* Rhz = (const float*)d_in[14];
    const float* Bhz = (const float*)d_in[15];
    const float* Wxn = (const float*)d_in[16];
    const float* Rxn = (const float*)d_in[17];
    const float* Bxn = (const float*)d_in[18];
    // d_in[19..21] (W_hn/root_hn/b_hn) are dead in the reference.
    float* out = (float*)d_out;
    (void)in_sizes; (void)n_in; (void)out_size;

    cudaFuncSetAttribute(k_gemm_mma, cudaFuncAttributeMaxDynamicSharedMemorySize,
                         2 * STAGE);

    k_zero<<<(Nn + 255) / 256, 256>>>();
    k_edge<<<(Ee + 255) / 256, 256>>>(attr, ei);
    k_scan<<<1, 1024>>>();
    k_fill<<<(Ee + 255) / 256, 256>>>(ei);
    k_scatter<<<Nn, 96>>>(x, hidden, ei);
    k_transpose<<<dim3(250, 5), 256>>>(Wxr, Wxz, Wxn, Whr, Whz);
    k_gemm_mma<<<282, 256, 2 * STAGE>>>();
    k_gates<<<(Nn + 3) / 4, 256>>>(x, hidden, Rxr, Bxr, Rxz, Bxz, Rxn, Bxn,
                                   Rhr, Bhr, Rhz, Bhz, out);
}

// round 11
// speedup vs baseline: 3.2444x; 1.2823x over previous
#include <cuda_runtime.h>
#include <cuda_bf16.h>
#include <math.h>
#include <stdint.h>

#define Nn   6000
#define Ee   192000
#define CINc 32
#define CHID 64
#define Kk   125
#define KX   4000        // Kk*CINc
#define KH   8000        // Kk*CHID

// ---------------- device scratch ----------------
__device__ __nv_bfloat16 g_Tx[(size_t)Nn * KX];   // bf16, pre-scaled by 1/deg
__device__ __nv_bfloat16 g_Th[(size_t)Nn * KH];
__device__ __nv_bfloat16 g_Btx[192 * KX];         // [co,k]: {Wxr,Wxz,Wxn} transposed
__device__ __nv_bfloat16 g_Bth[128 * KH];         // [co,k]: {Whr,Whz} transposed
__device__ float g_part[7][Nn * CHID];            // 0=XR 1=XZ 2=XN 3,4=HR halves 5,6=HZ halves
__device__ int   g_deg[Nn];
__device__ int   g_fill[Nn];
__device__ int   g_rowstart[Nn + 1];
__device__ int   g_csr[Ee];
__device__ int   g_bidx[Ee * 8];
__device__ float g_bval[Ee * 8];

// ---------------- PTX helpers (compute_103-safe: sm_80+ features only) ----------------
__device__ __forceinline__ uint32_t smem_u32(const void* p) {
    uint32_t a;
    asm("{ .reg .u64 t; cvta.to.shared.u64 t, %1; cvt.u32.u64 %0, t; }" : "=r"(a) : "l"(p));
    return a;
}
__device__ __forceinline__ void cpasync16(uint32_t dst, const void* src, int src_bytes) {
    asm volatile("cp.async.cg.shared.global [%0], [%1], 16, %2;"
                 :: "r"(dst), "l"(src), "r"(src_bytes) : "memory");
}
#define CP_COMMIT() asm volatile("cp.async.commit_group;" ::: "memory")
#define WAITG(n)    asm volatile("cp.async.wait_group " #n ";" ::: "memory")

__device__ __forceinline__ uint32_t lds32(uint32_t a) {
    uint32_t v;
    asm volatile("ld.shared.b32 %0, [%1];" : "=r"(v) : "r"(a));
    return v;
}
__device__ __forceinline__ void mma16(float* d, const uint32_t* a, uint32_t b0, uint32_t b1) {
    asm volatile(
        "mma.sync.aligned.m16n8k16.row.col.f32.bf16.bf16.f32 "
        "{%0,%1,%2,%3}, {%4,%5,%6,%7}, {%8,%9}, {%0,%1,%2,%3};"
        : "+f"(d[0]), "+f"(d[1]), "+f"(d[2]), "+f"(d[3])
        : "r"(a[0]), "r"(a[1]), "r"(a[2]), "r"(a[3]), "r"(b0), "r"(b1));
}

// ---------------- kernel 0: zero per-call counters ----------------
__global__ void k_zero() {
    int i = blockIdx.x * blockDim.x + threadIdx.x;
    if (i < Nn) { g_deg[i] = 0; g_fill[i] = 0; }
}

// ---------------- kernel 1: per-edge basis/index + degree histogram ----------------
__global__ void k_edge(const float* __restrict__ attr, const int* __restrict__ ei) {
    int e = blockIdx.x * blockDim.x + threadIdx.x;
    if (e >= Ee) return;
    float fr[3]; int i0[3];
#pragma unroll
    for (int d = 0; d < 3; d++) {
        float u = attr[e * 3 + d] * 4.0f;
        int i = (int)floorf(u);
        i = i < 0 ? 0 : (i > 3 ? 3 : i);
        fr[d] = u - (float)i;
        i0[d] = i;
    }
#pragma unroll
    for (int s = 0; s < 8; s++) {
        int b0 = s & 1, b1 = (s >> 1) & 1, b2 = (s >> 2) & 1;
        int idx = (i0[0] + b0) * 25 + (i0[1] + b1) * 5 + (i0[2] + b2);
        float w = (b0 ? fr[0] : 1.0f - fr[0]) *
                  (b1 ? fr[1] : 1.0f - fr[1]) *
                  (b2 ? fr[2] : 1.0f - fr[2]);
        g_bidx[e * 8 + s] = idx;
        g_bval[e * 8 + s] = w;
    }
    atomicAdd(&g_deg[ei[Ee + e]], 1);
}

// ---------------- kernel 2: exclusive scan (single block) ----------------
__global__ void k_scan() {
    __shared__ int sh[1024];
    int tid = threadIdx.x;
    const int CH = 6;
    int base = tid * CH;
    int local[CH];
    int sum = 0;
#pragma unroll
    for (int q = 0; q < CH; q++) {
        int i = base + q;
        int v = (i < Nn) ? g_deg[i] : 0;
        local[q] = sum;
        sum += v;
    }
    sh[tid] = sum;
    __syncthreads();
    for (int off = 1; off < 1024; off <<= 1) {
        int v = 0;
        if (tid >= off) v = sh[tid - off];
        __syncthreads();
        sh[tid] += v;
        __syncthreads();
    }
    int excl = (tid > 0) ? sh[tid - 1] : 0;
#pragma unroll
    for (int q = 0; q < CH; q++) {
        int i = base + q;
        if (i < Nn) g_rowstart[i] = excl + local[q];
    }
    if (tid == 1023) g_rowstart[Nn] = sh[1023];
}

// ---------------- kernel 3: CSR fill ----------------
__global__ void k_fill(const int* __restrict__ ei) {
    int e = blockIdx.x * blockDim.x + threadIdx.x;
    if (e >= Ee) return;
    int dst = ei[Ee + e];
    int p = atomicAdd(&g_fill[dst], 1);
    g_csr[g_rowstart[dst] + p] = e;
}

// ---------------- kernel 4: per-node scatter into T (fp32 smem accum, bf16 out) ----------------
__global__ __launch_bounds__(96) void k_scatter(const float* __restrict__ x,
                                                const float* __restrict__ hidden,
                                                const int* __restrict__ ei) {
    __shared__ float Tsh[Kk * 96];
    int n = blockIdx.x;
    int c = threadIdx.x;
#pragma unroll 5
    for (int k = 0; k < Kk; k++) Tsh[k * 96 + c] = 0.0f;
    int rs = g_rowstart[n], re = g_rowstart[n + 1];
    float inv = 1.0f / (float)max(re - rs, 1);
    __syncthreads();

    for (int j = rs; j < re; j++) {
        int e   = __ldg(&g_csr[j]);
        int src = __ldg(&ei[e]);
        float xv = (c < CINc) ? __ldg(&x[src * CINc + c])
                              : __ldg(&hidden[src * CHID + (c - CINc)]);
        const int4*   bip = (const int4*)(g_bidx + e * 8);
        const float4* bvp = (const float4*)(g_bval + e * 8);
        int4   ia = __ldg(bip),     ib = __ldg(bip + 1);
        float4 va = __ldg(bvp),     vb = __ldg(bvp + 1);
        Tsh[ia.x * 96 + c] += va.x * xv;
        Tsh[ia.y * 96 + c] += va.y * xv;
        Tsh[ia.z * 96 + c] += va.z * xv;
        Tsh[ia.w * 96 + c] += va.w * xv;
        Tsh[ib.x * 96 + c] += vb.x * xv;
        Tsh[ib.y * 96 + c] += vb.y * xv;
        Tsh[ib.z * 96 + c] += vb.z * xv;
        Tsh[ib.w * 96 + c] += vb.w * xv;
    }
    __syncthreads();

    if (c < CINc) {
        __nv_bfloat16* o = g_Tx + (size_t)n * KX + c;
#pragma unroll 5
        for (int k = 0; k < Kk; k++) o[k * CINc] = __float2bfloat16(Tsh[k * 96 + c] * inv);
    } else {
        __nv_bfloat16* o = g_Th + (size_t)n * KH + (c - CINc);
#pragma unroll 5
        for (int k = 0; k < Kk; k++) o[k * CHID] = __float2bfloat16(Tsh[k * 96 + c] * inv);
    }
}

// ---------------- kernel 5: transpose W -> Bt [N,K] K-major, bf16 ----------------
__global__ void k_transpose(const float* __restrict__ Wxr, const float* __restrict__ Wxz,
                            const float* __restrict__ Wxn, const float* __restrict__ Whr,
                            const float* __restrict__ Whz) {
    __shared__ float sh[32][65];
    int conv = blockIdx.y;
    const float* W; __nv_bfloat16* dst; int Kd;
    switch (conv) {
        case 0:  W = Wxr; dst = g_Btx;                     Kd = KX; break;
        case 1:  W = Wxz; dst = g_Btx + (size_t)64 * KX;   Kd = KX; break;
        case 2:  W = Wxn; dst = g_Btx + (size_t)128 * KX;  Kd = KX; break;
        case 3:  W = Whr; dst = g_Bth;                     Kd = KH; break;
        default: W = Whz; dst = g_Bth + (size_t)64 * KH;   Kd = KH; break;
    }
    int k0 = blockIdx.x * 32;
    if (k0 >= Kd) return;
    int tid = threadIdx.x;
#pragma unroll
    for (int w = 0; w < 8; w++) {
        int idx = w * 256 + tid, kk = idx >> 6, c = idx & 63;
        sh[kk][c] = W[(size_t)(k0 + kk) * 64 + c];
    }
    __syncthreads();
#pragma unroll
    for (int w = 0; w < 8; w++) {
        int idx = w * 256 + tid, c = idx >> 5, kk = idx & 31;
        dst[(size_t)c * Kd + k0 + kk] = __float2bfloat16(sh[kk][c]);
    }
}

// ---------------- kernel 6: bf16 mma.sync GEMM ----------------
// BM=64, BK=32 (bf16), 256 threads = 8 warps (2M x 4N), 4-stage cp.async pipeline.
// Smem rows padded to 80B (40 halves): 16B-aligned cp.async, stride 20 words is
// coprime-ish with 32 banks -> conflict-free fragment LDS.
// Stage: A 64*80=5120B, B NG*64*80 (NG=3 max: 15360B). STAGE=20480, 4 stages = 80KB.
#define STAGE 20480
#define NSTG  4

template<int NG>
__device__ __forceinline__ void gemm_body(const __nv_bfloat16* __restrict__ A,
                                          const __nv_bfloat16* __restrict__ Bt,
                                          int Kd, int kc0, int row0,
                                          int pbase, int pstride, uint32_t sb) {
    const int NT = NG * 2;                       // 8-wide N subtiles per warp
    int t = threadIdx.x;
    int w = t >> 5, lane = t & 31;
    int wm = w & 1, wn = w >> 1;
    int gid = lane >> 2, tig = lane & 3;

    float acc[2][NT][4];
#pragma unroll
    for (int mt = 0; mt < 2; mt++)
#pragma unroll
        for (int nt = 0; nt < NT; nt++)
#pragma unroll
            for (int q = 0; q < 4; q++) acc[mt][nt][q] = 0.0f;

    auto ldchunk = [&](int kc, int s) {
        uint32_t Ab = sb + s * STAGE;
        uint32_t Bb = Ab + 5120;
        int kb = kc * 32;
        {   // A: 64 rows x 64B = 256 x 16B, one per thread
            int row = t >> 2, c4 = t & 3;
            int m = row0 + row;
            int mc = m < Nn ? m : 0;
            cpasync16(Ab + (uint32_t)(row * 80 + c4 * 16),
                      A + (size_t)mc * Kd + kb + c4 * 8, m < Nn ? 16 : 0);
        }
#pragma unroll
        for (int q = 0; q < NG; q++) {           // B: NG*64 rows x 64B
            int idx = q * 256 + t, row = idx >> 2, c4 = idx & 3;
            cpasync16(Bb + (uint32_t)(row * 80 + c4 * 16),
                      Bt + (size_t)row * Kd + kb + c4 * 8, 16);
        }
        CP_COMMIT();
    };

    auto compute = [&](int s) {
        uint32_t Ab = sb + s * STAGE;
        uint32_t Bb = Ab + 5120;
#pragma unroll
        for (int ks = 0; ks < 2; ks++) {         // two k16 steps per 32-wide chunk
            uint32_t af[2][4];
#pragma unroll
            for (int mt = 0; mt < 2; mt++) {
                uint32_t base = Ab + (uint32_t)((wm * 32 + mt * 16 + gid) * 80 +
                                                ks * 32 + tig * 4);
                af[mt][0] = lds32(base);            // (row g,   k 2tig..+1)
                af[mt][1] = lds32(base + 8 * 80);   // (row g+8)
                af[mt][2] = lds32(base + 16);       // (row g,   k+8)
                af[mt][3] = lds32(base + 8 * 80 + 16);
            }
#pragma unroll
            for (int nt = 0; nt < NT; nt++) {
                uint32_t bb = Bb + (uint32_t)((wn * NT * 8 + nt * 8 + gid) * 80 +
                                              ks * 32 + tig * 4);
                uint32_t b0 = lds32(bb);            // B[n=gid][k 2tig..+1]
                uint32_t b1 = lds32(bb + 16);       // k+8
#pragma unroll
                for (int mt = 0; mt < 2; mt++)
                    mma16(acc[mt][nt], af[mt], b0, b1);
            }
        }
    };

    ldchunk(kc0, 0);
    ldchunk(kc0 + 1, 1);
    ldchunk(kc0 + 2, 2);
#pragma unroll 1
    for (int i = 0; i < 125; i++) {
        WAITG(2);
        __syncthreads();
        if (i + 3 < 125) ldchunk(kc0 + i + 3, (i + 3) & 3);
        else             CP_COMMIT();            // keep group count uniform for WAITG
        compute(i & 3);
    }

    // epilogue: c0,c1 -> (row g, cols 2tig,2tig+1); c2,c3 -> row g+8
#pragma unroll
    for (int mt = 0; mt < 2; mt++)
#pragma unroll
        for (int nt = 0; nt < NT; nt++) {
            int gcol = wn * NT * 8 + nt * 8 + tig * 2;
            int g = gcol >> 6, cc = gcol & 63;
            float* O = g_part[pbase + g * pstride];
            int r = row0 + wm * 32 + mt * 16 + gid;
            if (r < Nn)
                *(float2*)&O[(size_t)r * 64 + cc] =
                    make_float2(acc[mt][nt][0], acc[mt][nt][1]);
            if (r + 8 < Nn)
                *(float2*)&O[(size_t)(r + 8) * 64 + cc] =
                    make_float2(acc[mt][nt][2], acc[mt][nt][3]);
        }
}

// grid = 282: blocks [0,188) h-pass (94 M-tiles x 2 K-halves), [188,282) x-pass.
__global__ void __launch_bounds__(256, 2) k_gemm_mma() {
    extern __shared__ char smem[];
    uint32_t sb = smem_u32(smem);
    int bx = blockIdx.x;
    if (bx < 188) {
        int mt = bx >> 1, half = bx & 1;
        gemm_body<2>(g_Th, g_Bth, KH, half * 125, mt * 64, 3 + half, 2, sb);
    } else {
        gemm_body<3>(g_Tx, g_Btx, KX, 0, (bx - 188) * 64, 0, 1, sb);
    }
}

// ---------------- kernel 7: root GEMVs (fp32) + bias + GRU gates ----------------
__global__ void k_gates(const float* __restrict__ x, const float* __restrict__ hidden,
                        const float* __restrict__ Rxr, const float* __restrict__ Bxr,
                        const float* __restrict__ Rxz, const float* __restrict__ Bxz,
                        const float* __restrict__ Rxn, const float* __restrict__ Bxn,
                        const float* __restrict__ Rhr, const float* __restrict__ Bhr,
                        const float* __restrict__ Rhz, const float* __restrict__ Bhz,
                        float* __restrict__ out) {
    __shared__ float xs[4][32];
    __shared__ float hs[4][64];
    int tid = threadIdx.x;
    int nb = blockIdx.x * 4;
    if (tid < 128) {
        int nl = tid >> 5, i = tid & 31, n = nb + nl;
        xs[nl][i] = (n < Nn) ? x[n * 32 + i] : 0.f;
    }
    {
        int nl = tid >> 6, c = tid & 63, n = nb + nl;
        hs[nl][c] = (n < Nn) ? hidden[n * 64 + c] : 0.f;
    }
    __syncthreads();
    int nl = tid >> 6, c = tid & 63, n = nb + nl;
    if (n >= Nn) return;
    size_t i = (size_t)n * 64 + c;
    float xr = g_part[0][i] + Bxr[c];
    float xz = g_part[1][i] + Bxz[c];
    float xn = g_part[2][i] + Bxn[c];
    float hr = g_part[3][i] + g_part[4][i] + Bhr[c];
    float hz = g_part[5][i] + g_part[6][i] + Bhz[c];
#pragma unroll 8
    for (int k = 0; k < 32; k++) {
        float xv = xs[nl][k];
        xr += xv * Rxr[k * 64 + c];
        xz += xv * Rxz[k * 64 + c];
        xn += xv * Rxn[k * 64 + c];
    }
#pragma unroll 8
    for (int k = 0; k < 64; k++) {
        float hv = hs[nl][k];
        hr += hv * Rhr[k * 64 + c];
        hz += hv * Rhz[k * 64 + c];
    }
    float r = 1.0f / (1.0f + expf(-(xr + hr)));
    float z = 1.0f / (1.0f + expf(-(xz + hz)));
    float nno = tanhf(xn + r * hr);                 // faithful hr reuse
    out[i] = (1.0f - z) * nno + z * hs[nl][c];
}

// ---------------- launch ----------------
extern "C" void kernel_launch(void* const* d_in, const int* in_sizes, int n_in,
                              void* d_out, int out_size) {
    const float* x      = (const float*)d_in[0];
    const float* hidden = (const float*)d_in[1];
    const int*   ei     = (const int*)d_in[2];
    const float* attr   = (const float*)d_in[3];
    const float* Wxr = (const float*)d_in[4];
    const float* Rxr = (const float*)d_in[5];
    const float* Bxr = (const float*)d_in[6];
    const float* Whr = (const float*)d_in[7];
    const float* Rhr = (const float*)d_in[8];
    const float* Bhr = (const float*)d_in[9];
    const float* Wxz = (const float*)d_in[10];
    const float* Rxz = (const float*)d_in[11];
    const float* Bxz = (const float*)d_in[12];
    const float* Whz = (const float*)d_in[13];
    const float* Rhz = (const float*)d_in[14];
    const float* Bhz = (const float*)d_in[15];
    const float* Wxn = (const float*)d_in[16];
    const float* Rxn = (const float*)d_in[17];
    const float* Bxn = (const float*)d_in[18];
    // d_in[19..21] (W_hn/root_hn/b_hn) are dead in the reference.
    float* out = (float*)d_out;
    (void)in_sizes; (void)n_in; (void)out_size;

    cudaFuncSetAttribute(k_gemm_mma, cudaFuncAttributeMaxDynamicSharedMemorySize,
                         NSTG * STAGE);

    k_zero<<<(Nn + 255) / 256, 256>>>();
    k_edge<<<(Ee + 255) / 256, 256>>>(attr, ei);
    k_scan<<<1, 1024>>>();
    k_fill<<<(Ee + 255) / 256, 256>>>(ei);
    k_scatter<<<Nn, 96>>>(x, hidden, ei);
    k_transpose<<<dim3(250, 5), 256>>>(Wxr, Wxz, Wxn, Whr, Whz);
    k_gemm_mma<<<282, 256, NSTG * STAGE>>>();
    k_gates<<<(Nn + 3) / 4, 256>>>(x, hidden, Rxr, Bxr, Rxz, Bxz, Rxn, Bxn,
                                   Rhr, Bhr, Rhz, Bhz, out);
}